// round 1
// baseline (speedup 1.0000x reference)
#include <cuda_runtime.h>
#include <cstdint>

// Scratch (static device globals — no allocation).
__device__ float g_Tpart[8][32][8192];   // 8 MB: pose-chunk partials of T[b][g]
__device__ float g_pp[128][32][64];      // 1 MB: per-block partial pooled (pre-scale)

// ---- packed f32x2 helpers (Blackwell) ----
__device__ __forceinline__ unsigned long long pack2(float x, float y) {
    unsigned long long r;
    asm("mov.b64 %0, {%1,%2};" : "=l"(r) : "f"(x), "f"(y));
    return r;
}
__device__ __forceinline__ void fma2(unsigned long long& d, unsigned long long a, unsigned long long b) {
    asm("fma.rn.f32x2 %0, %1, %2, %0;" : "+l"(d) : "l"(a), "l"(b));
}
__device__ __forceinline__ float2 unpk(unsigned long long v) {
    float2 r;
    asm("mov.b64 {%0,%1}, %2;" : "=f"(r.x), "=f"(r.y) : "l"(v));
    return r;
}

// ============================================================================
// Stage 1: T[b, g] = sum_pose (CP[b, i] @ Wc[i])[x],  i = pose*128 + g/64,
//          x = g%64.  Pose dim split into 8 chunks -> g_Tpart.
// Grid: 1024 blocks = j(128) x pg(8).  Block: 64 threads = b(32) x rh(2).
// Thread owns a 4x8 output tile (rows r = rh*4..rh*4+3, all 8 cols) as 16 f32x2.
// ============================================================================
__global__ void __launch_bounds__(64) k_stage1(const float* __restrict__ cp,
                                               const float* __restrict__ wc) {
    const int blk = blockIdx.x;
    const int j   = blk >> 3;     // 0..127
    const int pg  = blk & 7;      // 0..7
    const int tid = threadIdx.x;  // 0..63
    const int b   = tid >> 1;     // 0..31
    const int rh  = tid & 1;      // row half

    __shared__ float4 sW4[128];   // 8 poses x 64 floats (one W matrix each)

    // Stage the 8 W matrices for this (j, pose-chunk): 128 float4, 2 per thread.
    {
        const float4* wc4 = reinterpret_cast<const float4*>(wc);
        const int v0 = tid, v1 = tid + 64;
        const int q0 = v0 >> 4, f0 = v0 & 15;
        const int q1 = v1 >> 4, f1 = v1 & 15;
        sW4[v0] = wc4[(size_t)((pg * 8 + q0) * 128 + j) * 16 + f0];
        sW4[v1] = wc4[(size_t)((pg * 8 + q1) * 128 + j) * 16 + f1];
    }
    __syncthreads();

    unsigned long long acc[4][4];  // [r'][colpair]
#pragma unroll
    for (int r = 0; r < 4; ++r)
#pragma unroll
        for (int c = 0; c < 4; ++c) acc[r][c] = 0ull;

#pragma unroll 2
    for (int q = 0; q < 8; ++q) {
        const int i = (pg * 8 + q) * 128 + j;
        const float4* a4 =
            reinterpret_cast<const float4*>(cp + ((size_t)b * 8192 + i) * 64 + rh * 32);
        float Ar[4][8];
#pragma unroll
        for (int t = 0; t < 8; ++t) {
            float4 v = a4[t];
            Ar[t >> 1][(t & 1) * 4 + 0] = v.x;
            Ar[t >> 1][(t & 1) * 4 + 1] = v.y;
            Ar[t >> 1][(t & 1) * 4 + 2] = v.z;
            Ar[t >> 1][(t & 1) * 4 + 3] = v.w;
        }
        // W for this pose: warp-uniform smem addresses -> broadcast LDS.
        const unsigned long long* w2 =
            reinterpret_cast<const unsigned long long*>(sW4 + q * 16);
#pragma unroll
        for (int m = 0; m < 8; ++m) {
            const unsigned long long wm0 = w2[m * 4 + 0];
            const unsigned long long wm1 = w2[m * 4 + 1];
            const unsigned long long wm2 = w2[m * 4 + 2];
            const unsigned long long wm3 = w2[m * 4 + 3];
#pragma unroll
            for (int r = 0; r < 4; ++r) {
                const unsigned long long ap = pack2(Ar[r][m], Ar[r][m]);
                fma2(acc[r][0], ap, wm0);
                fma2(acc[r][1], ap, wm1);
                fma2(acc[r][2], ap, wm2);
                fma2(acc[r][3], ap, wm3);
            }
        }
    }

    float* dst = &g_Tpart[pg][b][j * 64 + rh * 32];
#pragma unroll
    for (int r = 0; r < 4; ++r) {
        float2 p0 = unpk(acc[r][0]), p1 = unpk(acc[r][1]);
        float2 p2 = unpk(acc[r][2]), p3 = unpk(acc[r][3]);
        float4* d4 = reinterpret_cast<float4*>(dst + r * 8);
        d4[0] = make_float4(p0.x, p0.y, p1.x, p1.y);
        d4[1] = make_float4(p2.x, p2.y, p3.x, p3.y);
    }
}

// ============================================================================
// Stage 2: fold pose-chunk partials, then
//   P2[b, c'] = sum_g T[b,g] * E[g*256 + c']   (c' in [0,256))
//   g_pp[blk][b][c] = sum_{c' == c mod 64} P2[b, c']   (Esum fold)
// Grid: 128 blocks x 256 threads; block owns 64 consecutive g.
// ============================================================================
__global__ void __launch_bounds__(256) k_stage2(const float* __restrict__ E) {
    const int g0  = blockIdx.x * 64;
    const int tid = threadIdx.x;
    __shared__ float sT[64][34];     // T[b][g0+gg] transposed: sT[gg][b]
    __shared__ float sAcc[256][34];  // per-thread acc rows for the c-fold

#pragma unroll
    for (int k = 0; k < 8; ++k) {
        const int e = k * 256 + tid;
        const int b = e >> 6, gg = e & 63;
        float s = 0.f;
#pragma unroll
        for (int pg = 0; pg < 8; ++pg) s += g_Tpart[pg][b][g0 + gg];
        sT[gg][b] = s;
    }
    __syncthreads();

    unsigned long long acc[16];  // pairs over b: {P2[2bb], P2[2bb+1]} at c'=tid
#pragma unroll
    for (int i = 0; i < 16; ++i) acc[i] = 0ull;

    const float* Ecol = E + (size_t)g0 * 256 + tid;
#pragma unroll 4
    for (int gg = 0; gg < 64; ++gg) {
        const float ev = Ecol[(size_t)gg * 256];
        const unsigned long long ep = pack2(ev, ev);
        const unsigned long long* t2 =
            reinterpret_cast<const unsigned long long*>(&sT[gg][0]);
#pragma unroll
        for (int bb = 0; bb < 16; ++bb) fma2(acc[bb], t2[bb], ep);
    }

    {
        float2* row = reinterpret_cast<float2*>(&sAcc[tid][0]);
#pragma unroll
        for (int bb = 0; bb < 16; ++bb) row[bb] = unpk(acc[bb]);
    }
    __syncthreads();

    // Fold c' -> c = c' mod 64 and write per-block partial pooled.
#pragma unroll
    for (int k = 0; k < 8; ++k) {
        const int e = k * 256 + tid;
        const int c = e & 63, b = e >> 6;
        const float v = sAcc[c][b] + sAcc[c + 64][b] + sAcc[c + 128][b] + sAcc[c + 192][b];
        g_pp[blockIdx.x][b][c] = v;
    }
}

// ============================================================================
// Stage 3: pooled[b,c] = (sum_blk g_pp[blk][b][c]) / 64;
//          npc = pooled + rel;  out[b,o] = npc(8x8) @ w_next[o].
// Grid: 32 blocks (one per b) x 256 threads.
// ============================================================================
__global__ void __launch_bounds__(256) k_stage3(const float* __restrict__ wn,
                                                const float* __restrict__ rel,
                                                float* __restrict__ out) {
    const int b   = blockIdx.x;
    const int tid = threadIdx.x;
    const int c   = tid & 63, q = tid >> 6;  // q in 0..3
    __shared__ float sN[64];
    __shared__ float sP[4][64];
    __shared__ float sWn[4096];

    float s = 0.f;
#pragma unroll 8
    for (int k = 0; k < 32; ++k) s += g_pp[q * 32 + k][b][c];
    sP[q][c] = s;

    {
        float4* s4 = reinterpret_cast<float4*>(sWn);
        const float4* w4 = reinterpret_cast<const float4*>(wn);
#pragma unroll
        for (int k = 0; k < 4; ++k) s4[k * 256 + tid] = w4[k * 256 + tid];
    }
    __syncthreads();
    if (tid < 64) {
        sN[tid] = (sP[0][tid] + sP[1][tid] + sP[2][tid] + sP[3][tid]) * (1.f / 64.f)
                  + rel[tid];
    }
    __syncthreads();

    const int r = c >> 3, col = c & 7;
    float a[8];
#pragma unroll
    for (int m = 0; m < 8; ++m) a[m] = sN[r * 8 + m];
    float* ob = out + (size_t)b * 4096;
#pragma unroll 4
    for (int o = q * 16; o < q * 16 + 16; ++o) {
        float accv = 0.f;
#pragma unroll
        for (int m = 0; m < 8; ++m) accv += a[m] * sWn[o * 64 + m * 8 + col];
        ob[o * 64 + c] = accv;
    }
}

extern "C" void kernel_launch(void* const* d_in, const int* in_sizes, int n_in,
                              void* d_out, int out_size) {
    const float* cp  = (const float*)d_in[0];  // current_pose (32,8192,64)
    const float* wc  = (const float*)d_in[1];  // w_current    (8192,8,8)
    const float* wn  = (const float*)d_in[2];  // w_next       (64,8,8)
    const float* E   = (const float*)d_in[3];  // E_proj       (32,256,256)
    const float* rel = (const float*)d_in[4];  // rel_embedd   (64)
    float* out = (float*)d_out;                // (32,1,64,64) fp32

    k_stage1<<<1024, 64>>>(cp, wc);
    k_stage2<<<128, 256>>>(E);
    k_stage3<<<32, 256>>>(wn, rel, out);
}